// round 12
// baseline (speedup 1.0000x reference)
#include <cuda_runtime.h>
#include <cuda_bf16.h>
#include <math.h>
#include <stdint.h>

#define BB 4
#define CC 512
#define CQd 128      // C/4
#define NN 4096      // H*W

#define LTP 40       // proj smem row stride (BK=32 + 8 pad)
#define LTE 136      // energy smem row stride (BK=128 + 8 pad)
#define LTM 72       // PV smem row stride (BK=64 + 8 pad)
#define NSTAGE 3
#define STAGE_HALFS (128 * LTM)
#define DSMEM_BYTES (2 * NSTAGE * STAGE_HALFS * 2)   // 110592 B (PV)
#define EN_DSM (2 * 128 * LTE * 2)                   // 69632 B (energy)

typedef __nv_bfloat16 bf16;

// ---------------------------------------------------------------------------
// Scratch. T-layouts: q,k:[B][N][CQ]  v:[B][C][N]  P:[B][N][N] (exp, unnorm)
// ---------------------------------------------------------------------------
__device__ bf16  g_q[(size_t)BB * NN * CQd];
__device__ bf16  g_k[(size_t)BB * NN * CQd];
__device__ bf16  g_v[(size_t)BB * CC * NN];
__device__ bf16  g_P[(size_t)BB * NN * NN];
__device__ float g_part[(size_t)BB * NN * 32];

__device__ __forceinline__ uint32_t packbf(float a, float b) {
    __nv_bfloat162 t = __floats2bfloat162_rn(a, b);
    return *(uint32_t*)&t;
}
__device__ __forceinline__ float ex2(float x) {
    float r; asm("ex2.approx.f32 %0, %1;" : "=f"(r) : "f"(x)); return r;
}
__device__ __forceinline__ void cp16(uint32_t dst, const void* src) {
    asm volatile("cp.async.cg.shared.global [%0], [%1], 16;" :: "r"(dst), "l"(src));
}
__device__ __forceinline__ void cp_commit() {
    asm volatile("cp.async.commit_group;" ::: "memory");
}
__device__ __forceinline__ void cp_wait1() {
    asm volatile("cp.async.wait_group 1;" ::: "memory");
}
__device__ __forceinline__ void cp_wait0() {
    asm volatile("cp.async.wait_group 0;" ::: "memory");
}

__device__ __forceinline__ void ldsm4(uint32_t* d, uint32_t addr) {
    asm volatile("ldmatrix.sync.aligned.m8n8.x4.shared.b16 {%0,%1,%2,%3},[%4];"
                 : "=r"(d[0]), "=r"(d[1]), "=r"(d[2]), "=r"(d[3]) : "r"(addr));
}
__device__ __forceinline__ void mma16816(float* c, const uint32_t* a,
                                         const uint32_t* bfr) {
    asm volatile(
        "mma.sync.aligned.m16n8k16.row.col.f32.bf16.bf16.f32 "
        "{%0,%1,%2,%3},{%4,%5,%6,%7},{%8,%9},{%0,%1,%2,%3};"
        : "+f"(c[0]), "+f"(c[1]), "+f"(c[2]), "+f"(c[3])
        : "r"(a[0]), "r"(a[1]), "r"(a[2]), "r"(a[3]),
          "r"(bfr[0]), "r"(bfr[1]));
}

// ---------------------------------------------------------------------------
// Warp compute: warp tile 64x32 of m16n8k16, A-fragment double-buffered.
// ---------------------------------------------------------------------------
template <int LT, int KSTEPS>
__device__ __forceinline__ void mma_chunk(uint32_t aS, uint32_t bS,
                                          int wm, int wn, int lane,
                                          float (*acc)[4][4])
{
    const int arow = lane & 15;
    const int acol = (lane >> 4) * 8;
    const int brow = (lane & 7) + ((lane >> 4) << 3);
    const int bcol = ((lane >> 3) & 1) * 8;

    #pragma unroll
    for (int ks = 0; ks < KSTEPS; ks++) {
        const int k16 = ks * 16;
        uint32_t bfr[4][2];
        #pragma unroll
        for (int nj = 0; nj < 2; nj++) {
            uint32_t r4[4];
            ldsm4(r4, bS + (uint32_t)(((wn + nj * 16 + brow) * LT) + k16 + bcol) * 2u);
            bfr[nj * 2][0] = r4[0]; bfr[nj * 2][1] = r4[1];
            bfr[nj * 2 + 1][0] = r4[2]; bfr[nj * 2 + 1][1] = r4[3];
        }
        uint32_t a2[2][4];
        ldsm4(a2[0], aS + (uint32_t)(((wm + arow) * LT) + k16 + acol) * 2u);
        #pragma unroll
        for (int mi = 0; mi < 4; mi++) {
            if (mi < 3)
                ldsm4(a2[(mi + 1) & 1],
                      aS + (uint32_t)(((wm + (mi + 1) * 16 + arow) * LT) + k16 + acol) * 2u);
            #pragma unroll
            for (int ni = 0; ni < 4; ni++)
                mma16816(acc[mi][ni], a2[mi & 1], bfr[ni]);
        }
    }
}

// ---------------------------------------------------------------------------
// PV: 128(c) x 128(n), K=4096, BK=64, 3-stage pipe, 2 CTAs/SM.
// Grid: x = c-tile (FASTEST -> 4 concurrent CTAs share one P tile in L2),
//       y = n-tile, z = batch.
// invS computed inline from partials (reduce kernel eliminated).
// out (fp32) = gamma * acc * invS[col] + vt
// ---------------------------------------------------------------------------
__global__ __launch_bounds__(256, 2)
void gemm_pv(const bf16* __restrict__ A, const bf16* __restrict__ B,
             float* __restrict__ Cv, const float* __restrict__ add,
             const float* __restrict__ gammap, const float* __restrict__ part)
{
    extern __shared__ bf16 dsm[];
    __shared__ float s_invS[128];

    const int b  = blockIdx.z;
    const int m0 = blockIdx.x * 128;      // c-tile: fastest
    const int n0 = blockIdx.y * 128;      // n-tile
    const bf16* Ab = A + (long)b * CC * NN + (long)m0 * NN;
    const bf16* Bb = B + (long)b * NN * NN + (long)n0 * NN;

    const int tid  = threadIdx.x;
    const int lane = tid & 31;
    const int warp = tid >> 5;
    const int wm = (warp >> 2) * 64;
    const int wn = (warp & 3) * 32;

    const uint32_t asm0 = (uint32_t)__cvta_generic_to_shared(&dsm[0]);
    const uint32_t bsm0 = asm0 + (uint32_t)(NSTAGE * STAGE_HALFS) * 2u;
    const uint32_t stageB = (uint32_t)STAGE_HALFS * 2u;

    const int lr = tid >> 3;
    const int lk = (tid & 7) * 8;

    float acc[4][4][4];
    #pragma unroll
    for (int mi = 0; mi < 4; mi++)
        #pragma unroll
        for (int ni = 0; ni < 4; ni++)
            #pragma unroll
            for (int r = 0; r < 4; r++) acc[mi][ni][r] = 0.0f;

    const int nk = NN >> 6;   // 64

    #pragma unroll
    for (int s = 0; s < 2; s++) {
        const int k0 = s << 6;
        const uint32_t ao = asm0 + s * stageB;
        const uint32_t bo = bsm0 + s * stageB;
        #pragma unroll
        for (int i = 0; i < 4; i++) {
            int r = lr + i * 32;
            cp16(ao + (uint32_t)(r * LTM + lk) * 2u, Ab + (long)r * NN + k0 + lk);
            cp16(bo + (uint32_t)(r * LTM + lk) * 2u, Bb + (long)r * NN + k0 + lk);
        }
        cp_commit();
    }

    // inline invS for this CTA's 128 columns (overlaps pipeline warm-up;
    // the first mainloop __syncthreads publishes it before any epilogue read)
    if (tid < 128) {
        const float* p = part + ((long)b * NN + n0 + tid) * 32;
        float s = 0.0f;
        #pragma unroll
        for (int i = 0; i < 32; i++) s += p[i];
        s_invS[tid] = 1.0f / s;
    }

    int stage = 0;
    for (int ki = 0; ki < nk; ki++) {
        cp_wait1();
        __syncthreads();
        if (ki + 2 < nk) {
            const int ns = (stage + 2 >= NSTAGE) ? (stage + 2 - NSTAGE) : (stage + 2);
            const int k0 = (ki + 2) << 6;
            const uint32_t ao = asm0 + ns * stageB;
            const uint32_t bo = bsm0 + ns * stageB;
            #pragma unroll
            for (int i = 0; i < 4; i++) {
                int r = lr + i * 32;
                cp16(ao + (uint32_t)(r * LTM + lk) * 2u, Ab + (long)r * NN + k0 + lk);
                cp16(bo + (uint32_t)(r * LTM + lk) * 2u, Bb + (long)r * NN + k0 + lk);
            }
            cp_commit();
        } else {
            cp_commit();
        }
        mma_chunk<LTM, 4>(asm0 + stage * stageB, bsm0 + stage * stageB, wm, wn, lane, acc);
        stage = (stage + 1 == NSTAGE) ? 0 : stage + 1;
    }

    const int g  = lane >> 2;
    const int tg = lane & 3;
    float* Cb = Cv + (long)b * CC * NN;
    const float gm = gammap[0];
    const float* addb = add + (long)b * CC * NN;
    #pragma unroll
    for (int mi = 0; mi < 4; mi++)
        #pragma unroll
        for (int half = 0; half < 2; half++) {
            const int row = m0 + wm + mi * 16 + g + half * 8;
            #pragma unroll
            for (int ni = 0; ni < 4; ni++) {
                const int cl = wn + ni * 8 + 2 * tg;
                const long off = (long)row * NN + n0 + cl;
                float2 r = *(const float2*)&addb[off];
                float2 v;
                v.x = fmaf(gm * s_invS[cl],     acc[mi][ni][half * 2],     r.x);
                v.y = fmaf(gm * s_invS[cl + 1], acc[mi][ni][half * 2 + 1], r.y);
                *(float2*)&Cb[off] = v;
            }
        }
}

// ---------------------------------------------------------------------------
// Energy: 128x128 tile, whole K=128 in ONE chunk (8 k16 steps), 2 CTAs/SM.
// P (bf16) = exp2(scale2 * q.k); per-row partial sums.
// ---------------------------------------------------------------------------
__global__ __launch_bounds__(256, 2)
void gemm_energy(const bf16* __restrict__ A, const bf16* __restrict__ B,
                 bf16* __restrict__ C, float* __restrict__ part, float scale2)
{
    extern __shared__ bf16 dsm[];
    __shared__ float rowsum[128];

    const int b  = blockIdx.z;
    const int m0 = blockIdx.y * 128;
    const int n0 = blockIdx.x * 128;
    const bf16* Ab = A + (long)b * NN * CQd + (long)m0 * CQd;
    const bf16* Bb = B + (long)b * NN * CQd + (long)n0 * CQd;

    const int tid  = threadIdx.x;
    const int lane = tid & 31;
    const int warp = tid >> 5;
    const int wm = (warp >> 2) * 64;
    const int wn = (warp & 3) * 32;

    const uint32_t aS = (uint32_t)__cvta_generic_to_shared(&dsm[0]);
    const uint32_t bS = aS + (uint32_t)(128 * LTE) * 2u;

    if (tid < 128) rowsum[tid] = 0.0f;

    #pragma unroll
    for (int i = 0; i < 8; i++) {
        int idx = tid + 256 * i;
        int r = idx >> 4, kc = (idx & 15) * 8;
        cp16(aS + (uint32_t)(r * LTE + kc) * 2u, Ab + (long)r * CQd + kc);
        cp16(bS + (uint32_t)(r * LTE + kc) * 2u, Bb + (long)r * CQd + kc);
    }
    cp_commit();

    float acc[4][4][4];
    #pragma unroll
    for (int mi = 0; mi < 4; mi++)
        #pragma unroll
        for (int ni = 0; ni < 4; ni++)
            #pragma unroll
            for (int r = 0; r < 4; r++) acc[mi][ni][r] = 0.0f;

    cp_wait0();
    __syncthreads();
    mma_chunk<LTE, 8>(aS, bS, wm, wn, lane, acc);

    const int g  = lane >> 2;
    const int tg = lane & 3;
    bf16* Cb = C + (long)b * NN * NN;
    __syncthreads();
    #pragma unroll
    for (int mi = 0; mi < 4; mi++)
        #pragma unroll
        for (int half = 0; half < 2; half++) {
            const int rl = wm + mi * 16 + g + half * 8;
            const int row = m0 + rl;
            float rs = 0.0f;
            #pragma unroll
            for (int ni = 0; ni < 4; ni++) {
                const int col = n0 + wn + ni * 8 + 2 * tg;
                float e0 = ex2(scale2 * acc[mi][ni][half * 2]);
                float e1 = ex2(scale2 * acc[mi][ni][half * 2 + 1]);
                __nv_bfloat162 t = __floats2bfloat162_rn(e0, e1);
                *(__nv_bfloat162*)(Cb + (long)row * NN + col) = t;
                rs += __bfloat162float(t.x) + __bfloat162float(t.y);
            }
            rs += __shfl_xor_sync(0xffffffffu, rs, 1);
            rs += __shfl_xor_sync(0xffffffffu, rs, 2);
            if (tg == 0) atomicAdd(&rowsum[rl], rs);
        }
    __syncthreads();
    if (tid < 128)
        part[((long)b * NN + m0 + tid) * gridDim.x + blockIdx.x] = rowsum[tid];
}

// ---------------------------------------------------------------------------
// ALL projections in ONE launch. 768 CTAs, 256 threads.
// ---------------------------------------------------------------------------
__global__ __launch_bounds__(256, 2)
void gemm_proj_all(const float* __restrict__ vt, const float* __restrict__ vs,
                   const float* __restrict__ Wq, const float* __restrict__ Wk,
                   const float* __restrict__ Wv,
                   bf16* __restrict__ qout, bf16* __restrict__ kout,
                   bf16* __restrict__ vout, float scale)
{
    __shared__ bf16 As[128 * LTP];
    __shared__ bf16 Bs[128 * LTP];

    const int bid = blockIdx.x;
    const bool isqk = (bid < 256);

    const float* Arow;
    const float* Atrp;
    bf16* Cb;
    int m0, n0, ldc;
    bool a_is_trans;

    if (isqk) {
        const int slice = bid >> 5;
        const int type  = slice >> 2;
        const int b     = slice & 3;
        m0  = (bid & 31) * 128;
        n0  = 0;
        ldc = CQd;
        Atrp = (type ? vs : vt) + (long)b * CC * NN;
        Arow = type ? Wk : Wq;
        Cb   = (type ? kout : qout) + (long)b * NN * CQd;
        a_is_trans = true;
    } else {
        const int i = bid - 256;
        const int b = i >> 7;
        m0  = ((i & 127) >> 5) * 128;
        n0  = (i & 31) * 128;
        ldc = NN;
        Arow = Wv;
        Atrp = vs + (long)b * CC * NN;
        Cb   = vout + (long)b * CC * NN;
        a_is_trans = false;
    }

    const int tid  = threadIdx.x;
    const int lane = tid & 31;
    const int warp = tid >> 5;
    const int wm = (warp >> 2) * 64;
    const int wn = (warp & 3) * 32;

    const uint32_t asm0 = (uint32_t)__cvta_generic_to_shared(&As[0]);
    const uint32_t bsm0 = (uint32_t)__cvta_generic_to_shared(&Bs[0]);

    float acc[4][4][4];
    #pragma unroll
    for (int mi = 0; mi < 4; mi++)
        #pragma unroll
        for (int ni = 0; ni < 4; ni++)
            #pragma unroll
            for (int r = 0; r < 4; r++) acc[mi][ni][r] = 0.0f;

    for (int k0 = 0; k0 < CC; k0 += 32) {
        __syncthreads();
        if (a_is_trans) {
            #pragma unroll
            for (int i2 = 0; i2 < 4; i2++) {
                int idx = tid + 256 * i2;
                int m = idx & 127, kq = idx >> 7;
                float x0 = Atrp[(long)(k0 + kq * 4 + 0) * NN + m0 + m];
                float x1 = Atrp[(long)(k0 + kq * 4 + 1) * NN + m0 + m];
                float x2 = Atrp[(long)(k0 + kq * 4 + 2) * NN + m0 + m];
                float x3 = Atrp[(long)(k0 + kq * 4 + 3) * NN + m0 + m];
                uint2 p; p.x = packbf(x0, x1); p.y = packbf(x2, x3);
                *(uint2*)&As[m * LTP + kq * 4] = p;
            }
            #pragma unroll
            for (int i2 = 0; i2 < 4; i2++) {
                int idx = tid + 256 * i2;
                int r = idx >> 3, k4 = (idx & 7) * 4;
                float4 v = *(const float4*)&Arow[(long)r * CC + k0 + k4];
                uint2 p; p.x = packbf(v.x, v.y); p.y = packbf(v.z, v.w);
                *(uint2*)&Bs[r * LTP + k4] = p;
            }
        } else {
            #pragma unroll
            for (int i2 = 0; i2 < 4; i2++) {
                int idx = tid + 256 * i2;
                int r = idx >> 3, k4 = (idx & 7) * 4;
                float4 v = *(const float4*)&Arow[(long)(m0 + r) * CC + k0 + k4];
                uint2 p; p.x = packbf(v.x, v.y); p.y = packbf(v.z, v.w);
                *(uint2*)&As[r * LTP + k4] = p;
            }
            #pragma unroll
            for (int i2 = 0; i2 < 4; i2++) {
                int idx = tid + 256 * i2;
                int m = idx & 127, kq = idx >> 7;
                float x0 = Atrp[(long)(k0 + kq * 4 + 0) * NN + n0 + m];
                float x1 = Atrp[(long)(k0 + kq * 4 + 1) * NN + n0 + m];
                float x2 = Atrp[(long)(k0 + kq * 4 + 2) * NN + n0 + m];
                float x3 = Atrp[(long)(k0 + kq * 4 + 3) * NN + n0 + m];
                uint2 p; p.x = packbf(x0, x1); p.y = packbf(x2, x3);
                *(uint2*)&Bs[m * LTP + kq * 4] = p;
            }
        }
        __syncthreads();
        mma_chunk<LTP, 2>(asm0, bsm0, wm, wn, lane, acc);
    }

    const int g  = lane >> 2;
    const int tg = lane & 3;
    #pragma unroll
    for (int mi = 0; mi < 4; mi++)
        #pragma unroll
        for (int half = 0; half < 2; half++) {
            const int row = m0 + wm + mi * 16 + g + half * 8;
            #pragma unroll
            for (int ni = 0; ni < 4; ni++) {
                const int col = n0 + wn + ni * 8 + 2 * tg;
                uint32_t p = packbf(scale * acc[mi][ni][half * 2],
                                    scale * acc[mi][ni][half * 2 + 1]);
                *(uint32_t*)(Cb + (long)row * ldc + col) = p;
            }
        }
}

// ---------------------------------------------------------------------------
// Launcher
// ---------------------------------------------------------------------------
extern "C" void kernel_launch(void* const* d_in, const int* in_sizes, int n_in,
                              void* d_out, int out_size)
{
    const float* vt    = (const float*)d_in[0];
    const float* vs    = (const float*)d_in[1];
    const float* Wq    = (const float*)d_in[2];
    const float* Wk    = (const float*)d_in[3];
    const float* Wv    = (const float*)d_in[4];
    const float* gamma = (const float*)d_in[5];
    float* out = (float*)d_out;

    bf16 *qp, *kp, *vp, *Pp;
    float *partp;
    cudaGetSymbolAddress((void**)&qp, g_q);
    cudaGetSymbolAddress((void**)&kp, g_k);
    cudaGetSymbolAddress((void**)&vp, g_v);
    cudaGetSymbolAddress((void**)&Pp, g_P);
    cudaGetSymbolAddress((void**)&partp, g_part);

    static int attr_done = 0;
    if (!attr_done) {
        cudaFuncSetAttribute(gemm_pv,
                             cudaFuncAttributeMaxDynamicSharedMemorySize, DSMEM_BYTES);
        cudaFuncSetAttribute(gemm_energy,
                             cudaFuncAttributeMaxDynamicSharedMemorySize, EN_DSM);
        attr_done = 1;
    }

    const float eq_scale    = 1.0f / sqrtf((float)CC);
    const float attn_scale2 = (1.0f / sqrtf((float)CC)) * 1.4426950408889634f;

    // 1) all projections, one launch (768 CTAs)
    gemm_proj_all<<<768, 256>>>(vt, vs, Wq, Wk, Wv, qp, kp, vp, eq_scale);

    // 2) energy+exp: single-chunk K=128, P bf16, 32 partials/row
    gemm_energy<<<dim3(32, 32, BB), 256, EN_DSM>>>(qp, kp, Pp, partp, attn_scale2);

    // 3) PV + residual (invS computed inline from partials)
    gemm_pv<<<dim3(4, 32, BB), 256, DSMEM_BYTES>>>(vp, Pp, out, vt, gamma, partp);
}

// round 13
// speedup vs baseline: 1.0537x; 1.0537x over previous
#include <cuda_runtime.h>
#include <cuda_bf16.h>
#include <math.h>
#include <stdint.h>

#define BB 4
#define CC 512
#define CQd 128      // C/4
#define NN 4096      // H*W

#define LTP 72       // proj smem row stride (BK=64 + 8 pad)
#define LTM 72       // main smem row stride (BK=64 + 8 pad)
#define NSTAGE 3
#define STAGE_HALFS (128 * LTM)
#define DSMEM_BYTES (2 * NSTAGE * STAGE_HALFS * 2)   // 110592 B

typedef __nv_bfloat16 bf16;

// ---------------------------------------------------------------------------
// Scratch. T-layouts: q,k:[B][N][CQ]  v:[B][C][N]  P:[B][N][N] (exp, unnorm)
// ---------------------------------------------------------------------------
__device__ bf16  g_q[(size_t)BB * NN * CQd];
__device__ bf16  g_k[(size_t)BB * NN * CQd];
__device__ bf16  g_v[(size_t)BB * CC * NN];
__device__ bf16  g_P[(size_t)BB * NN * NN];
__device__ float g_part[(size_t)BB * NN * 32];

__device__ __forceinline__ uint32_t packbf(float a, float b) {
    __nv_bfloat162 t = __floats2bfloat162_rn(a, b);
    return *(uint32_t*)&t;
}
__device__ __forceinline__ float ex2(float x) {
    float r; asm("ex2.approx.f32 %0, %1;" : "=f"(r) : "f"(x)); return r;
}
__device__ __forceinline__ void cp16(uint32_t dst, const void* src) {
    asm volatile("cp.async.cg.shared.global [%0], [%1], 16;" :: "r"(dst), "l"(src));
}
__device__ __forceinline__ void cp_commit() {
    asm volatile("cp.async.commit_group;" ::: "memory");
}
__device__ __forceinline__ void cp_wait1() {
    asm volatile("cp.async.wait_group 1;" ::: "memory");
}

// ---------------------------------------------------------------------------
// Warp compute (R9 plain version): warp tile 64x32 of m16n8k16.
// 8 warps 2(m) x 4(n). KSTEPS = BK/16.
// ---------------------------------------------------------------------------
template <int LT, int KSTEPS>
__device__ __forceinline__ void mma_chunk(uint32_t aS, uint32_t bS,
                                          int wm, int wn, int lane,
                                          float (*acc)[4][4])
{
    const int arow = lane & 15;
    const int acol = (lane >> 4) * 8;
    const int brow = (lane & 7) + ((lane >> 4) << 3);
    const int bcol = ((lane >> 3) & 1) * 8;

    #pragma unroll
    for (int ks = 0; ks < KSTEPS; ks++) {
        const int k16 = ks * 16;
        uint32_t bfr[4][2];
        #pragma unroll
        for (int nj = 0; nj < 2; nj++) {
            uint32_t addr = bS + (uint32_t)(((wn + nj * 16 + brow) * LT) + k16 + bcol) * 2u;
            uint32_t r0, r1, r2, r3;
            asm volatile("ldmatrix.sync.aligned.m8n8.x4.shared.b16 {%0,%1,%2,%3},[%4];"
                         : "=r"(r0), "=r"(r1), "=r"(r2), "=r"(r3) : "r"(addr));
            bfr[nj * 2][0] = r0; bfr[nj * 2][1] = r1;
            bfr[nj * 2 + 1][0] = r2; bfr[nj * 2 + 1][1] = r3;
        }
        #pragma unroll
        for (int mi = 0; mi < 4; mi++) {
            uint32_t addr = aS + (uint32_t)(((wm + mi * 16 + arow) * LT) + k16 + acol) * 2u;
            uint32_t a0, a1, a2, a3;
            asm volatile("ldmatrix.sync.aligned.m8n8.x4.shared.b16 {%0,%1,%2,%3},[%4];"
                         : "=r"(a0), "=r"(a1), "=r"(a2), "=r"(a3) : "r"(addr));
            #pragma unroll
            for (int ni = 0; ni < 4; ni++) {
                asm volatile(
                    "mma.sync.aligned.m16n8k16.row.col.f32.bf16.bf16.f32 "
                    "{%0,%1,%2,%3},{%4,%5,%6,%7},{%8,%9},{%0,%1,%2,%3};"
                    : "+f"(acc[mi][ni][0]), "+f"(acc[mi][ni][1]),
                      "+f"(acc[mi][ni][2]), "+f"(acc[mi][ni][3])
                    : "r"(a0), "r"(a1), "r"(a2), "r"(a3),
                      "r"(bfr[ni][0]), "r"(bfr[ni][1]));
            }
        }
    }
}

// ---------------------------------------------------------------------------
// Main bf16 GEMM (energy / PV), 128x128 tile, BK=64, 3-stage cp.async pipe.
// R9 structure; EPI=1 adds inline invS from partials (reduce kernel removed).
//   EPI=0 (energy): C (bf16) = exp2(scale2*acc); per-row partial sums.
//   EPI=1 (PV)    : C (fp32) = gamma[0] * acc * invS[col] + add
// ---------------------------------------------------------------------------
template <int EPI>
__global__ __launch_bounds__(256, 2)
void gemm_main(const bf16* __restrict__ A, const bf16* __restrict__ B,
               void* __restrict__ Cv, const float* __restrict__ add,
               const float* __restrict__ gammap,
               float* __restrict__ part,
               int K, int lda, int ldb, int ldc,
               long sA, long sB, long sC, float scale)
{
    extern __shared__ bf16 dsm[];
    __shared__ float rowsum[128];      // EPI=0: rowsum; EPI=1: s_invS

    const int b  = blockIdx.z;
    const bf16* Ab = A + (long)b * sA + (long)blockIdx.y * 128 * lda;
    const bf16* Bb = B + (long)b * sB + (long)blockIdx.x * 128 * ldb;

    const int tid  = threadIdx.x;
    const int lane = tid & 31;
    const int warp = tid >> 5;
    const int wm = (warp >> 2) * 64;
    const int wn = (warp & 3) * 32;

    const uint32_t asm0 = (uint32_t)__cvta_generic_to_shared(&dsm[0]);
    const uint32_t bsm0 = asm0 + (uint32_t)(NSTAGE * STAGE_HALFS) * 2u;
    const uint32_t stageB = (uint32_t)STAGE_HALFS * 2u;

    const int lr = tid >> 3;
    const int lk = (tid & 7) * 8;

    if (EPI == 0) {
        if (tid < 128) rowsum[tid] = 0.0f;
    }

    float acc[4][4][4];
    #pragma unroll
    for (int mi = 0; mi < 4; mi++)
        #pragma unroll
        for (int ni = 0; ni < 4; ni++)
            #pragma unroll
            for (int r = 0; r < 4; r++) acc[mi][ni][r] = 0.0f;

    const int nk = K >> 6;

    #pragma unroll
    for (int s = 0; s < 2; s++) {
        const int k0 = s << 6;
        const uint32_t ao = asm0 + s * stageB;
        const uint32_t bo = bsm0 + s * stageB;
        #pragma unroll
        for (int i = 0; i < 4; i++) {
            int r = lr + i * 32;
            cp16(ao + (uint32_t)(r * LTM + lk) * 2u, Ab + (long)r * lda + k0 + lk);
            cp16(bo + (uint32_t)(r * LTM + lk) * 2u, Bb + (long)r * ldb + k0 + lk);
        }
        cp_commit();
    }

    // PV: inline invS for this CTA's 128 columns, overlapped with warm-up.
    // Published by the first mainloop __syncthreads; only read in epilogue.
    if (EPI == 1) {
        if (tid < 128) {
            const float* p = part + ((long)b * NN + blockIdx.x * 128 + tid) * 32;
            float s = 0.0f;
            #pragma unroll
            for (int i = 0; i < 32; i++) s += p[i];
            rowsum[tid] = 1.0f / s;
        }
    }

    int stage = 0;
    for (int ki = 0; ki < nk; ki++) {
        cp_wait1();
        __syncthreads();
        if (ki + 2 < nk) {
            const int ns = (stage + 2 >= NSTAGE) ? (stage + 2 - NSTAGE) : (stage + 2);
            const int k0 = (ki + 2) << 6;
            const uint32_t ao = asm0 + ns * stageB;
            const uint32_t bo = bsm0 + ns * stageB;
            #pragma unroll
            for (int i = 0; i < 4; i++) {
                int r = lr + i * 32;
                cp16(ao + (uint32_t)(r * LTM + lk) * 2u, Ab + (long)r * lda + k0 + lk);
                cp16(bo + (uint32_t)(r * LTM + lk) * 2u, Bb + (long)r * ldb + k0 + lk);
            }
            cp_commit();
        } else {
            cp_commit();
        }
        mma_chunk<LTM, 4>(asm0 + stage * stageB, bsm0 + stage * stageB, wm, wn, lane, acc);
        stage = (stage + 1 == NSTAGE) ? 0 : stage + 1;
    }

    const int g  = lane >> 2;
    const int tg = lane & 3;
    const int m0 = blockIdx.y * 128;
    const int n0 = blockIdx.x * 128;

    if (EPI == 0) {
        __syncthreads();
        bf16* Cb = (bf16*)Cv + (long)b * sC;
        #pragma unroll
        for (int mi = 0; mi < 4; mi++)
            #pragma unroll
            for (int half = 0; half < 2; half++) {
                const int rl = wm + mi * 16 + g + half * 8;
                const int row = m0 + rl;
                float rs = 0.0f;
                #pragma unroll
                for (int ni = 0; ni < 4; ni++) {
                    const int col = n0 + wn + ni * 8 + 2 * tg;
                    float e0 = ex2(scale * acc[mi][ni][half * 2]);
                    float e1 = ex2(scale * acc[mi][ni][half * 2 + 1]);
                    __nv_bfloat162 t = __floats2bfloat162_rn(e0, e1);
                    *(__nv_bfloat162*)(Cb + (long)row * ldc + col) = t;
                    rs += __bfloat162float(t.x) + __bfloat162float(t.y);
                }
                rs += __shfl_xor_sync(0xffffffffu, rs, 1);
                rs += __shfl_xor_sync(0xffffffffu, rs, 2);
                if (tg == 0) atomicAdd(&rowsum[rl], rs);
            }
        __syncthreads();
        if (tid < 128)
            part[((long)b * NN + m0 + tid) * gridDim.x + blockIdx.x] = rowsum[tid];
    } else {
        float* Cb = (float*)Cv + (long)b * sC;
        const float gm = gammap[0];
        const float* addb = add + (long)b * sC;
        #pragma unroll
        for (int mi = 0; mi < 4; mi++)
            #pragma unroll
            for (int half = 0; half < 2; half++) {
                const int row = m0 + wm + mi * 16 + g + half * 8;
                #pragma unroll
                for (int ni = 0; ni < 4; ni++) {
                    const int cl = wn + ni * 8 + 2 * tg;
                    const long off = (long)row * ldc + n0 + cl;
                    float2 r = *(const float2*)&addb[off];
                    float2 v;
                    v.x = fmaf(gm * rowsum[cl],     acc[mi][ni][half * 2],     r.x);
                    v.y = fmaf(gm * rowsum[cl + 1], acc[mi][ni][half * 2 + 1], r.y);
                    *(float2*)&Cb[off] = v;
                }
            }
    }
}

// ---------------------------------------------------------------------------
// ALL projections in ONE launch. 768 CTAs, 256 threads. BK=64 (8 iterations).
// ---------------------------------------------------------------------------
__global__ __launch_bounds__(256, 2)
void gemm_proj_all(const float* __restrict__ vt, const float* __restrict__ vs,
                   const float* __restrict__ Wq, const float* __restrict__ Wk,
                   const float* __restrict__ Wv,
                   bf16* __restrict__ qout, bf16* __restrict__ kout,
                   bf16* __restrict__ vout, float scale)
{
    __shared__ bf16 As[128 * LTP];
    __shared__ bf16 Bs[128 * LTP];

    const int bid = blockIdx.x;
    const bool isqk = (bid < 256);

    const float* Arow;
    const float* Atrp;
    bf16* Cb;
    int m0, n0, ldc;
    bool a_is_trans;

    if (isqk) {
        const int slice = bid >> 5;
        const int type  = slice >> 2;
        const int b     = slice & 3;
        m0  = (bid & 31) * 128;
        n0  = 0;
        ldc = CQd;
        Atrp = (type ? vs : vt) + (long)b * CC * NN;
        Arow = type ? Wk : Wq;
        Cb   = (type ? kout : qout) + (long)b * NN * CQd;
        a_is_trans = true;
    } else {
        const int i = bid - 256;
        const int b = i >> 7;
        m0  = ((i & 127) >> 5) * 128;
        n0  = (i & 31) * 128;
        ldc = NN;
        Arow = Wv;
        Atrp = vs + (long)b * CC * NN;
        Cb   = vout + (long)b * CC * NN;
        a_is_trans = false;
    }

    const int tid  = threadIdx.x;
    const int lane = tid & 31;
    const int warp = tid >> 5;
    const int wm = (warp >> 2) * 64;
    const int wn = (warp & 3) * 32;

    const uint32_t asm0 = (uint32_t)__cvta_generic_to_shared(&As[0]);
    const uint32_t bsm0 = (uint32_t)__cvta_generic_to_shared(&Bs[0]);

    float acc[4][4][4];
    #pragma unroll
    for (int mi = 0; mi < 4; mi++)
        #pragma unroll
        for (int ni = 0; ni < 4; ni++)
            #pragma unroll
            for (int r = 0; r < 4; r++) acc[mi][ni][r] = 0.0f;

    for (int k0 = 0; k0 < CC; k0 += 64) {
        __syncthreads();
        if (a_is_trans) {
            // As <- transpose(Atrp[k][m0+m]): 128m x 64k, 8 uint2/thread
            #pragma unroll
            for (int i2 = 0; i2 < 8; i2++) {
                int idx = tid + 256 * i2;
                int m = idx & 127, kq = idx >> 7;     // kq 0..15
                float x0 = Atrp[(long)(k0 + kq * 4 + 0) * NN + m0 + m];
                float x1 = Atrp[(long)(k0 + kq * 4 + 1) * NN + m0 + m];
                float x2 = Atrp[(long)(k0 + kq * 4 + 2) * NN + m0 + m];
                float x3 = Atrp[(long)(k0 + kq * 4 + 3) * NN + m0 + m];
                uint2 p; p.x = packbf(x0, x1); p.y = packbf(x2, x3);
                *(uint2*)&As[m * LTP + kq * 4] = p;
            }
            // Bs <- W row-major: 128 rows x 64k
            #pragma unroll
            for (int i2 = 0; i2 < 8; i2++) {
                int idx = tid + 256 * i2;
                int r = idx >> 4, k4 = (idx & 15) * 4;
                float4 v = *(const float4*)&Arow[(long)r * CC + k0 + k4];
                uint2 p; p.x = packbf(v.x, v.y); p.y = packbf(v.z, v.w);
                *(uint2*)&Bs[r * LTP + k4] = p;
            }
        } else {
            #pragma unroll
            for (int i2 = 0; i2 < 8; i2++) {
                int idx = tid + 256 * i2;
                int r = idx >> 4, k4 = (idx & 15) * 4;
                float4 v = *(const float4*)&Arow[(long)(m0 + r) * CC + k0 + k4];
                uint2 p; p.x = packbf(v.x, v.y); p.y = packbf(v.z, v.w);
                *(uint2*)&As[r * LTP + k4] = p;
            }
            #pragma unroll
            for (int i2 = 0; i2 < 8; i2++) {
                int idx = tid + 256 * i2;
                int m = idx & 127, kq = idx >> 7;
                float x0 = Atrp[(long)(k0 + kq * 4 + 0) * NN + n0 + m];
                float x1 = Atrp[(long)(k0 + kq * 4 + 1) * NN + n0 + m];
                float x2 = Atrp[(long)(k0 + kq * 4 + 2) * NN + n0 + m];
                float x3 = Atrp[(long)(k0 + kq * 4 + 3) * NN + n0 + m];
                uint2 p; p.x = packbf(x0, x1); p.y = packbf(x2, x3);
                *(uint2*)&Bs[m * LTP + kq * 4] = p;
            }
        }
        __syncthreads();
        mma_chunk<LTP, 4>(asm0, bsm0, wm, wn, lane, acc);
    }

    const int g  = lane >> 2;
    const int tg = lane & 3;
    #pragma unroll
    for (int mi = 0; mi < 4; mi++)
        #pragma unroll
        for (int half = 0; half < 2; half++) {
            const int row = m0 + wm + mi * 16 + g + half * 8;
            #pragma unroll
            for (int ni = 0; ni < 4; ni++) {
                const int col = n0 + wn + ni * 8 + 2 * tg;
                uint32_t p = packbf(scale * acc[mi][ni][half * 2],
                                    scale * acc[mi][ni][half * 2 + 1]);
                *(uint32_t*)(Cb + (long)row * ldc + col) = p;
            }
        }
}

// ---------------------------------------------------------------------------
// Launcher
// ---------------------------------------------------------------------------
extern "C" void kernel_launch(void* const* d_in, const int* in_sizes, int n_in,
                              void* d_out, int out_size)
{
    const float* vt    = (const float*)d_in[0];
    const float* vs    = (const float*)d_in[1];
    const float* Wq    = (const float*)d_in[2];
    const float* Wk    = (const float*)d_in[3];
    const float* Wv    = (const float*)d_in[4];
    const float* gamma = (const float*)d_in[5];
    float* out = (float*)d_out;

    bf16 *qp, *kp, *vp, *Pp;
    float *partp;
    cudaGetSymbolAddress((void**)&qp, g_q);
    cudaGetSymbolAddress((void**)&kp, g_k);
    cudaGetSymbolAddress((void**)&vp, g_v);
    cudaGetSymbolAddress((void**)&Pp, g_P);
    cudaGetSymbolAddress((void**)&partp, g_part);

    static int attr_done = 0;
    if (!attr_done) {
        cudaFuncSetAttribute(gemm_main<0>,
                             cudaFuncAttributeMaxDynamicSharedMemorySize, DSMEM_BYTES);
        cudaFuncSetAttribute(gemm_main<1>,
                             cudaFuncAttributeMaxDynamicSharedMemorySize, DSMEM_BYTES);
        attr_done = 1;
    }

    const float eq_scale    = 1.0f / sqrtf((float)CC);
    const float attn_scale2 = (1.0f / sqrtf((float)CC)) * 1.4426950408889634f;

    // 1) all projections, one launch (768 CTAs), BK=64
    gemm_proj_all<<<768, 256>>>(vt, vs, Wq, Wk, Wv, qp, kp, vp, eq_scale);

    // 2) energy+exp: P[n][m] = exp2(attn_scale2 * q.k) bf16, 32 partials/row
    gemm_main<0><<<dim3(32, 32, BB), 256, DSMEM_BYTES>>>(
        qp, kp, Pp, nullptr, nullptr, partp,
        CQd, CQd, CQd, NN,
        (long)NN * CQd, (long)NN * CQd, (long)NN * NN, attn_scale2);

    // 3) PV + residual (invS inline from partials; R9 grid order: x=n fastest)
    gemm_main<1><<<dim3(32, 4, BB), 256, DSMEM_BYTES>>>(
        vp, Pp, out, vt, gamma, partp,
        NN, NN, NN, NN,
        (long)CC * NN, (long)NN * NN, (long)CC * NN, 1.0f);
}

// round 17
// speedup vs baseline: 1.0918x; 1.0362x over previous
#include <cuda_runtime.h>
#include <cuda_bf16.h>
#include <math.h>
#include <stdint.h>

#define BB 4
#define CC 512
#define CQd 128      // C/4
#define NN 4096      // H*W

#define LTP 72       // proj smem row stride (BK=64 + 8 pad)
#define LTM 72       // main smem row stride (BK=64 + 8 pad)
#define NSTAGE 3
#define STAGE_HALFS (128 * LTM)
#define DSMEM_BYTES (2 * NSTAGE * STAGE_HALFS * 2)   // 110592 B
#define STG_H 136    // staging stride (halfs) for bf16 tile: 128 + 8
#define STG_F 132    // staging stride (floats) for fp32 tile: 128 + 4

typedef __nv_bfloat16 bf16;

// ---------------------------------------------------------------------------
// Scratch. T-layouts: q,k:[B][N][CQ]  v:[B][C][N]  P:[B][N][N] (exp, unnorm)
// ---------------------------------------------------------------------------
__device__ bf16  g_q[(size_t)BB * NN * CQd];
__device__ bf16  g_k[(size_t)BB * NN * CQd];
__device__ bf16  g_v[(size_t)BB * CC * NN];
__device__ bf16  g_P[(size_t)BB * NN * NN];
__device__ float g_part[(size_t)BB * NN * 32];

__device__ __forceinline__ uint32_t packbf(float a, float b) {
    __nv_bfloat162 t = __floats2bfloat162_rn(a, b);
    return *(uint32_t*)&t;
}
__device__ __forceinline__ float ex2(float x) {
    float r; asm("ex2.approx.f32 %0, %1;" : "=f"(r) : "f"(x)); return r;
}
__device__ __forceinline__ void cp16(uint32_t dst, const void* src) {
    asm volatile("cp.async.cg.shared.global [%0], [%1], 16;" :: "r"(dst), "l"(src));
}
__device__ __forceinline__ void cp_commit() {
    asm volatile("cp.async.commit_group;" ::: "memory");
}
__device__ __forceinline__ void cp_wait1() {
    asm volatile("cp.async.wait_group 1;" ::: "memory");
}

// ---------------------------------------------------------------------------
// Warp compute: warp tile 64x32 of m16n8k16. 8 warps 2(m) x 4(n).
// ---------------------------------------------------------------------------
template <int LT, int KSTEPS>
__device__ __forceinline__ void mma_chunk(uint32_t aS, uint32_t bS,
                                          int wm, int wn, int lane,
                                          float (*acc)[4][4])
{
    const int arow = lane & 15;
    const int acol = (lane >> 4) * 8;
    const int brow = (lane & 7) + ((lane >> 4) << 3);
    const int bcol = ((lane >> 3) & 1) * 8;

    #pragma unroll
    for (int ks = 0; ks < KSTEPS; ks++) {
        const int k16 = ks * 16;
        uint32_t bfr[4][2];
        #pragma unroll
        for (int nj = 0; nj < 2; nj++) {
            uint32_t addr = bS + (uint32_t)(((wn + nj * 16 + brow) * LT) + k16 + bcol) * 2u;
            uint32_t r0, r1, r2, r3;
            asm volatile("ldmatrix.sync.aligned.m8n8.x4.shared.b16 {%0,%1,%2,%3},[%4];"
                         : "=r"(r0), "=r"(r1), "=r"(r2), "=r"(r3) : "r"(addr));
            bfr[nj * 2][0] = r0; bfr[nj * 2][1] = r1;
            bfr[nj * 2 + 1][0] = r2; bfr[nj * 2 + 1][1] = r3;
        }
        #pragma unroll
        for (int mi = 0; mi < 4; mi++) {
            uint32_t addr = aS + (uint32_t)(((wm + mi * 16 + arow) * LT) + k16 + acol) * 2u;
            uint32_t a0, a1, a2, a3;
            asm volatile("ldmatrix.sync.aligned.m8n8.x4.shared.b16 {%0,%1,%2,%3},[%4];"
                         : "=r"(a0), "=r"(a1), "=r"(a2), "=r"(a3) : "r"(addr));
            #pragma unroll
            for (int ni = 0; ni < 4; ni++) {
                asm volatile(
                    "mma.sync.aligned.m16n8k16.row.col.f32.bf16.bf16.f32 "
                    "{%0,%1,%2,%3},{%4,%5,%6,%7},{%8,%9},{%0,%1,%2,%3};"
                    : "+f"(acc[mi][ni][0]), "+f"(acc[mi][ni][1]),
                      "+f"(acc[mi][ni][2]), "+f"(acc[mi][ni][3])
                    : "r"(a0), "r"(a1), "r"(a2), "r"(a3),
                      "r"(bfr[ni][0]), "r"(bfr[ni][1]));
            }
        }
    }
}

// ---------------------------------------------------------------------------
// Main bf16 GEMM (energy / PV), 128x128 tile, BK=64, 3-stage cp.async pipe.
// Epilogues stage the C tile through (now-dead) pipeline smem and store with
// fully-coalesced row-major 16B accesses.
//   EPI=0 (energy): C (bf16) = exp2(scale2*acc); per-row partial sums.
//   EPI=1 (PV)    : C (fp32) = gamma[0] * acc * invS[col] + add
// ---------------------------------------------------------------------------
template <int EPI>
__global__ __launch_bounds__(256, 2)
void gemm_main(const bf16* __restrict__ A, const bf16* __restrict__ B,
               void* __restrict__ Cv, const float* __restrict__ add,
               const float* __restrict__ gammap,
               float* __restrict__ part,
               int K, int lda, int ldb, int ldc,
               long sA, long sB, long sC, float scale)
{
    extern __shared__ bf16 dsm[];
    __shared__ float rowsum[128];      // EPI=0: rowsum; EPI=1: s_invS

    const int b  = blockIdx.z;
    const bf16* Ab = A + (long)b * sA + (long)blockIdx.y * 128 * lda;
    const bf16* Bb = B + (long)b * sB + (long)blockIdx.x * 128 * ldb;

    const int tid  = threadIdx.x;
    const int lane = tid & 31;
    const int warp = tid >> 5;
    const int wm = (warp >> 2) * 64;
    const int wn = (warp & 3) * 32;

    const uint32_t asm0 = (uint32_t)__cvta_generic_to_shared(&dsm[0]);
    const uint32_t bsm0 = asm0 + (uint32_t)(NSTAGE * STAGE_HALFS) * 2u;
    const uint32_t stageB = (uint32_t)STAGE_HALFS * 2u;

    const int lr = tid >> 3;
    const int lk = (tid & 7) * 8;

    if (EPI == 0) {
        if (tid < 128) rowsum[tid] = 0.0f;
    }

    float acc[4][4][4];
    #pragma unroll
    for (int mi = 0; mi < 4; mi++)
        #pragma unroll
        for (int ni = 0; ni < 4; ni++)
            #pragma unroll
            for (int r = 0; r < 4; r++) acc[mi][ni][r] = 0.0f;

    const int nk = K >> 6;

    #pragma unroll
    for (int s = 0; s < 2; s++) {
        const int k0 = s << 6;
        const uint32_t ao = asm0 + s * stageB;
        const uint32_t bo = bsm0 + s * stageB;
        #pragma unroll
        for (int i = 0; i < 4; i++) {
            int r = lr + i * 32;
            cp16(ao + (uint32_t)(r * LTM + lk) * 2u, Ab + (long)r * lda + k0 + lk);
            cp16(bo + (uint32_t)(r * LTM + lk) * 2u, Bb + (long)r * ldb + k0 + lk);
        }
        cp_commit();
    }

    // PV: inline invS for this CTA's 128 columns, overlapped with warm-up.
    if (EPI == 1) {
        if (tid < 128) {
            const float* p = part + ((long)b * NN + blockIdx.x * 128 + tid) * 32;
            float s = 0.0f;
            #pragma unroll
            for (int i = 0; i < 32; i++) s += p[i];
            rowsum[tid] = 1.0f / s;
        }
    }

    int stage = 0;
    for (int ki = 0; ki < nk; ki++) {
        cp_wait1();
        __syncthreads();
        if (ki + 2 < nk) {
            const int ns = (stage + 2 >= NSTAGE) ? (stage + 2 - NSTAGE) : (stage + 2);
            const int k0 = (ki + 2) << 6;
            const uint32_t ao = asm0 + ns * stageB;
            const uint32_t bo = bsm0 + ns * stageB;
            #pragma unroll
            for (int i = 0; i < 4; i++) {
                int r = lr + i * 32;
                cp16(ao + (uint32_t)(r * LTM + lk) * 2u, Ab + (long)r * lda + k0 + lk);
                cp16(bo + (uint32_t)(r * LTM + lk) * 2u, Bb + (long)r * ldb + k0 + lk);
            }
            cp_commit();
        } else {
            cp_commit();
        }
        mma_chunk<LTM, 4>(asm0 + stage * stageB, bsm0 + stage * stageB, wm, wn, lane, acc);
        stage = (stage + 1 == NSTAGE) ? 0 : stage + 1;
    }

    const int g  = lane >> 2;
    const int tg = lane & 3;
    const int m0 = blockIdx.y * 128;
    const int n0 = blockIdx.x * 128;

    __syncthreads();   // mainloop done everywhere: pipeline smem is reusable

    if (EPI == 0) {
        // stage exp tile to smem + accumulate row sums
        bf16* stg = dsm;                               // [128][STG_H]
        #pragma unroll
        for (int mi = 0; mi < 4; mi++)
            #pragma unroll
            for (int half = 0; half < 2; half++) {
                const int rl = wm + mi * 16 + g + half * 8;
                float rs = 0.0f;
                #pragma unroll
                for (int ni = 0; ni < 4; ni++) {
                    const int cl = wn + ni * 8 + 2 * tg;
                    float e0 = ex2(scale * acc[mi][ni][half * 2]);
                    float e1 = ex2(scale * acc[mi][ni][half * 2 + 1]);
                    __nv_bfloat162 t = __floats2bfloat162_rn(e0, e1);
                    *(__nv_bfloat162*)&stg[rl * STG_H + cl] = t;
                    rs += __bfloat162float(t.x) + __bfloat162float(t.y);
                }
                rs += __shfl_xor_sync(0xffffffffu, rs, 1);
                rs += __shfl_xor_sync(0xffffffffu, rs, 2);
                if (tg == 0) atomicAdd(&rowsum[rl], rs);
            }
        __syncthreads();
        // coalesced store: 16 threads cover a 256B row
        bf16* Cb = (bf16*)Cv + (long)b * sC;
        #pragma unroll
        for (int p = 0; p < 8; p++) {
            int idx = tid + 256 * p;
            int r = idx >> 4, cg = (idx & 15) * 8;
            uint4 v = *(uint4*)&stg[r * STG_H + cg];
            *(uint4*)(Cb + (long)(m0 + r) * ldc + n0 + cg) = v;
        }
        if (tid < 128)
            part[((long)b * NN + m0 + tid) * gridDim.x + blockIdx.x] = rowsum[tid];
    } else {
        // stage gm*invS*acc (fp32) to smem
        float* stg = (float*)dsm;                      // [128][STG_F]
        const float gm = gammap[0];
        #pragma unroll
        for (int mi = 0; mi < 4; mi++)
            #pragma unroll
            for (int half = 0; half < 2; half++) {
                const int rl = wm + mi * 16 + g + half * 8;
                #pragma unroll
                for (int ni = 0; ni < 4; ni++) {
                    const int cl = wn + ni * 8 + 2 * tg;
                    float2 v;
                    v.x = gm * rowsum[cl]     * acc[mi][ni][half * 2];
                    v.y = gm * rowsum[cl + 1] * acc[mi][ni][half * 2 + 1];
                    *(float2*)&stg[rl * STG_F + cl] = v;
                }
            }
        __syncthreads();
        // coalesced residual add + store: 32 threads cover a 512B row
        float* Cb = (float*)Cv + (long)b * sC;
        const float* addb = add + (long)b * sC;
        #pragma unroll
        for (int p = 0; p < 16; p++) {
            int idx = tid + 256 * p;
            int r = idx >> 5, cg = (idx & 31) * 4;
            const long off = (long)(m0 + r) * ldc + n0 + cg;
            float4 s = *(float4*)&stg[r * STG_F + cg];
            float4 a = *(const float4*)&addb[off];
            s.x += a.x; s.y += a.y; s.z += a.z; s.w += a.w;
            *(float4*)&Cb[off] = s;
        }
    }
}

// ---------------------------------------------------------------------------
// ALL projections in ONE launch. 768 CTAs, 256 threads. BK=64.
// ---------------------------------------------------------------------------
__global__ __launch_bounds__(256, 2)
void gemm_proj_all(const float* __restrict__ vt, const float* __restrict__ vs,
                   const float* __restrict__ Wq, const float* __restrict__ Wk,
                   const float* __restrict__ Wv,
                   bf16* __restrict__ qout, bf16* __restrict__ kout,
                   bf16* __restrict__ vout, float scale)
{
    __shared__ bf16 As[128 * LTP];
    __shared__ bf16 Bs[128 * LTP];

    const int bid = blockIdx.x;
    const bool isqk = (bid < 256);

    const float* Arow;
    const float* Atrp;
    bf16* Cb;
    int m0, n0, ldc;
    bool a_is_trans;

    if (isqk) {
        const int slice = bid >> 5;
        const int type  = slice >> 2;
        const int b     = slice & 3;
        m0  = (bid & 31) * 128;
        n0  = 0;
        ldc = CQd;
        Atrp = (type ? vs : vt) + (long)b * CC * NN;
        Arow = type ? Wk : Wq;
        Cb   = (type ? kout : qout) + (long)b * NN * CQd;
        a_is_trans = true;
    } else {
        const int i = bid - 256;
        const int b = i >> 7;
        m0  = ((i & 127) >> 5) * 128;
        n0  = (i & 31) * 128;
        ldc = NN;
        Arow = Wv;
        Atrp = vs + (long)b * CC * NN;
        Cb   = vout + (long)b * CC * NN;
        a_is_trans = false;
    }

    const int tid  = threadIdx.x;
    const int lane = tid & 31;
    const int warp = tid >> 5;
    const int wm = (warp >> 2) * 64;
    const int wn = (warp & 3) * 32;

    const uint32_t asm0 = (uint32_t)__cvta_generic_to_shared(&As[0]);
    const uint32_t bsm0 = (uint32_t)__cvta_generic_to_shared(&Bs[0]);

    float acc[4][4][4];
    #pragma unroll
    for (int mi = 0; mi < 4; mi++)
        #pragma unroll
        for (int ni = 0; ni < 4; ni++)
            #pragma unroll
            for (int r = 0; r < 4; r++) acc[mi][ni][r] = 0.0f;

    for (int k0 = 0; k0 < CC; k0 += 64) {
        __syncthreads();
        if (a_is_trans) {
            #pragma unroll
            for (int i2 = 0; i2 < 8; i2++) {
                int idx = tid + 256 * i2;
                int m = idx & 127, kq = idx >> 7;
                float x0 = Atrp[(long)(k0 + kq * 4 + 0) * NN + m0 + m];
                float x1 = Atrp[(long)(k0 + kq * 4 + 1) * NN + m0 + m];
                float x2 = Atrp[(long)(k0 + kq * 4 + 2) * NN + m0 + m];
                float x3 = Atrp[(long)(k0 + kq * 4 + 3) * NN + m0 + m];
                uint2 p; p.x = packbf(x0, x1); p.y = packbf(x2, x3);
                *(uint2*)&As[m * LTP + kq * 4] = p;
            }
            #pragma unroll
            for (int i2 = 0; i2 < 8; i2++) {
                int idx = tid + 256 * i2;
                int r = idx >> 4, k4 = (idx & 15) * 4;
                float4 v = *(const float4*)&Arow[(long)r * CC + k0 + k4];
                uint2 p; p.x = packbf(v.x, v.y); p.y = packbf(v.z, v.w);
                *(uint2*)&Bs[r * LTP + k4] = p;
            }
        } else {
            #pragma unroll
            for (int i2 = 0; i2 < 8; i2++) {
                int idx = tid + 256 * i2;
                int r = idx >> 4, k4 = (idx & 15) * 4;
                float4 v = *(const float4*)&Arow[(long)(m0 + r) * CC + k0 + k4];
                uint2 p; p.x = packbf(v.x, v.y); p.y = packbf(v.z, v.w);
                *(uint2*)&As[r * LTP + k4] = p;
            }
            #pragma unroll
            for (int i2 = 0; i2 < 8; i2++) {
                int idx = tid + 256 * i2;
                int m = idx & 127, kq = idx >> 7;
                float x0 = Atrp[(long)(k0 + kq * 4 + 0) * NN + n0 + m];
                float x1 = Atrp[(long)(k0 + kq * 4 + 1) * NN + n0 + m];
                float x2 = Atrp[(long)(k0 + kq * 4 + 2) * NN + n0 + m];
                float x3 = Atrp[(long)(k0 + kq * 4 + 3) * NN + n0 + m];
                uint2 p; p.x = packbf(x0, x1); p.y = packbf(x2, x3);
                *(uint2*)&Bs[m * LTP + kq * 4] = p;
            }
        }
        __syncthreads();
        mma_chunk<LTP, 4>(asm0, bsm0, wm, wn, lane, acc);
    }

    const int g  = lane >> 2;
    const int tg = lane & 3;
    #pragma unroll
    for (int mi = 0; mi < 4; mi++)
        #pragma unroll
        for (int half = 0; half < 2; half++) {
            const int row = m0 + wm + mi * 16 + g + half * 8;
            #pragma unroll
            for (int ni = 0; ni < 4; ni++) {
                const int col = n0 + wn + ni * 8 + 2 * tg;
                uint32_t p = packbf(scale * acc[mi][ni][half * 2],
                                    scale * acc[mi][ni][half * 2 + 1]);
                *(uint32_t*)(Cb + (long)row * ldc + col) = p;
            }
        }
}

// ---------------------------------------------------------------------------
// Launcher
// ---------------------------------------------------------------------------
extern "C" void kernel_launch(void* const* d_in, const int* in_sizes, int n_in,
                              void* d_out, int out_size)
{
    const float* vt    = (const float*)d_in[0];
    const float* vs    = (const float*)d_in[1];
    const float* Wq    = (const float*)d_in[2];
    const float* Wk    = (const float*)d_in[3];
    const float* Wv    = (const float*)d_in[4];
    const float* gamma = (const float*)d_in[5];
    float* out = (float*)d_out;

    bf16 *qp, *kp, *vp, *Pp;
    float *partp;
    cudaGetSymbolAddress((void**)&qp, g_q);
    cudaGetSymbolAddress((void**)&kp, g_k);
    cudaGetSymbolAddress((void**)&vp, g_v);
    cudaGetSymbolAddress((void**)&Pp, g_P);
    cudaGetSymbolAddress((void**)&partp, g_part);

    static int attr_done = 0;
    if (!attr_done) {
        cudaFuncSetAttribute(gemm_main<0>,
                             cudaFuncAttributeMaxDynamicSharedMemorySize, DSMEM_BYTES);
        cudaFuncSetAttribute(gemm_main<1>,
                             cudaFuncAttributeMaxDynamicSharedMemorySize, DSMEM_BYTES);
        attr_done = 1;
    }

    const float eq_scale    = 1.0f / sqrtf((float)CC);
    const float attn_scale2 = (1.0f / sqrtf((float)CC)) * 1.4426950408889634f;

    // 1) all projections, one launch (768 CTAs), BK=64
    gemm_proj_all<<<768, 256>>>(vt, vs, Wq, Wk, Wv, qp, kp, vp, eq_scale);

    // 2) energy+exp: P[n][m] = exp2(attn_scale2 * q.k) bf16, 32 partials/row
    gemm_main<0><<<dim3(32, 32, BB), 256, DSMEM_BYTES>>>(
        qp, kp, Pp, nullptr, nullptr, partp,
        CQd, CQd, CQd, NN,
        (long)NN * CQd, (long)NN * CQd, (long)NN * NN, attn_scale2);

    // 3) PV + residual (invS inline from partials)
    gemm_main<1><<<dim3(32, 4, BB), 256, DSMEM_BYTES>>>(
        vp, Pp, out, vt, gamma, partp,
        NN, NN, NN, NN,
        (long)CC * NN, (long)NN * NN, (long)CC * NN, 1.0f);
}